// round 1
// baseline (speedup 1.0000x reference)
#include <cuda_runtime.h>

// ---------------------------------------------------------------------------
// LeWinAttention: x[8192,64,256] -> qkv -> windowed MHA (+rel-pos bias) -> proj
// Round 0: correct fp32 baseline, 3 kernels, FMA-pipe bound (~10 ms predicted).
// ---------------------------------------------------------------------------

#define BM 64
#define BN 64
#define BK 16

// Scratch (allocation-free rule: __device__ globals)
__device__ float g_qkv[402653184];   // 8192*64*768  (1.5 GB)
__device__ float g_aout[134217728];  // 8192*64*256  (512 MB)

// ---------------------------------------------------------------------------
// C[M,Nc] = A[M,256] @ W[Nc,256]^T + bias[Nc]
// Tiled 64x64, K-step 16, 256 threads, 4x4 register microtile.
// ---------------------------------------------------------------------------
__global__ void __launch_bounds__(256)
gemm_bias_kernel(const float* __restrict__ A, const float* __restrict__ W,
                 const float* __restrict__ bias, float* __restrict__ C, int Nc)
{
    __shared__ float AsT[BK][BM + 4];  // [k][m], +4 pad keeps float4 align + spreads banks
    __shared__ float BsT[BK][BN + 4];  // [k][n]

    const int t  = threadIdx.x;
    const int tx = t & 15;       // n-direction microtile index
    const int ty = t >> 4;       // m-direction microtile index
    const int lr = t >> 2;       // 0..63 : tile row for global loads
    const int lc = (t & 3) << 2; // 0,4,8,12 : k offset for global loads

    const size_t mBase = (size_t)blockIdx.y * BM;
    const int    nBase = blockIdx.x * BN;

    const float* Ap = A + (mBase + (size_t)lr) * 256 + lc;
    const float* Wp = W + ((size_t)nBase + lr) * 256 + lc;

    float acc[4][4];
#pragma unroll
    for (int i = 0; i < 4; i++)
#pragma unroll
        for (int j = 0; j < 4; j++) acc[i][j] = 0.f;

    for (int k0 = 0; k0 < 256; k0 += BK) {
        float4 av = *(const float4*)(Ap + k0);
        float4 bv = *(const float4*)(Wp + k0);
        __syncthreads();  // protect previous iteration's smem reads (WAR)
        AsT[lc + 0][lr] = av.x; AsT[lc + 1][lr] = av.y;
        AsT[lc + 2][lr] = av.z; AsT[lc + 3][lr] = av.w;
        BsT[lc + 0][lr] = bv.x; BsT[lc + 1][lr] = bv.y;
        BsT[lc + 2][lr] = bv.z; BsT[lc + 3][lr] = bv.w;
        __syncthreads();
#pragma unroll
        for (int kk = 0; kk < BK; kk++) {
            float4 a = *(const float4*)&AsT[kk][ty << 2];
            float4 b = *(const float4*)&BsT[kk][tx << 2];
            float af[4] = {a.x, a.y, a.z, a.w};
            float bf[4] = {b.x, b.y, b.z, b.w};
#pragma unroll
            for (int i = 0; i < 4; i++)
#pragma unroll
                for (int j = 0; j < 4; j++)
                    acc[i][j] += af[i] * bf[j];
        }
    }

    float4 bb = *(const float4*)(bias + nBase + (tx << 2));
#pragma unroll
    for (int i = 0; i < 4; i++) {
        float4 o;
        o.x = acc[i][0] + bb.x;
        o.y = acc[i][1] + bb.y;
        o.z = acc[i][2] + bb.z;
        o.w = acc[i][3] + bb.w;
        *(float4*)(C + (mBase + (ty << 2) + i) * (size_t)Nc + nBase + (tx << 2)) = o;
    }
}

// ---------------------------------------------------------------------------
// Attention: one CTA per (head h = blockIdx.x, window b = blockIdx.y).
// 128 threads. q/k/v tiles [64,32] staged in smem; scores + bias + softmax +
// P@V fully in-CTA; per-head output written to g_aout[b, n, h*32 + d].
// ---------------------------------------------------------------------------
__global__ void __launch_bounds__(128)
attn_kernel(const float* __restrict__ qkv, const float* __restrict__ table,
            const int* __restrict__ rpi, float* __restrict__ aout)
{
    __shared__ float sq[64][36];
    __shared__ float sk[64][36];
    __shared__ float sv[64][36];
    __shared__ float sp[64][65];

    const int h = blockIdx.x;
    const int b = blockIdx.y;
    const int t = threadIdx.x;

    // ---- load q, k, v for this (b, h): rows stride 768, cols h*32..h*32+31
    const float* base = qkv + (size_t)b * 64 * 768 + h * 32;
    for (int idx = t; idx < 64 * 8; idx += 128) {
        int n  = idx >> 3;
        int c4 = (idx & 7) << 2;
        const float* rp = base + n * 768 + c4;
        float4 q4 = *(const float4*)(rp);
        float4 k4 = *(const float4*)(rp + 256);
        float4 v4 = *(const float4*)(rp + 512);
        *(float4*)&sq[n][c4] = q4;
        *(float4*)&sk[n][c4] = k4;
        *(float4*)&sv[n][c4] = v4;
    }
    __syncthreads();

    const int n    = t & 63;   // token row this thread owns
    const int half = t >> 6;   // 0/1 : which half of m (scores) / d (output)

    // ---- cache q row in registers
    float qreg[32];
#pragma unroll
    for (int d4 = 0; d4 < 8; d4++) {
        float4 q4 = *(const float4*)&sq[n][d4 << 2];
        qreg[d4 * 4 + 0] = q4.x; qreg[d4 * 4 + 1] = q4.y;
        qreg[d4 * 4 + 2] = q4.z; qreg[d4 * 4 + 3] = q4.w;
    }

    // ---- scores: s[n][m] = scale * q.k + bias[h][n][m]
    const float scale = 0.17677669529663687f;  // 32^-0.5
#pragma unroll 4
    for (int mm = 0; mm < 32; mm++) {
        int m = (half << 5) + mm;
        float s = 0.f;
#pragma unroll
        for (int d4 = 0; d4 < 8; d4++) {
            float4 k4 = *(const float4*)&sk[m][d4 << 2];
            s += qreg[d4 * 4 + 0] * k4.x + qreg[d4 * 4 + 1] * k4.y
               + qreg[d4 * 4 + 2] * k4.z + qreg[d4 * 4 + 3] * k4.w;
        }
        int idx = rpi[n * 64 + m];
        sp[n][m] = s * scale + table[idx * 8 + h];
    }
    __syncthreads();

    // ---- softmax over m (one thread per row; threads 64..127 idle briefly)
    if (t < 64) {
        float mx = -1e30f;
#pragma unroll
        for (int m = 0; m < 64; m++) mx = fmaxf(mx, sp[t][m]);
        float sum = 0.f;
#pragma unroll
        for (int m = 0; m < 64; m++) {
            float e = __expf(sp[t][m] - mx);
            sp[t][m] = e;
            sum += e;
        }
        float inv = 1.f / sum;
#pragma unroll
        for (int m = 0; m < 64; m++) sp[t][m] *= inv;
    }
    __syncthreads();

    // ---- out[n][d] = sum_m p[n][m] * v[m][d]   (thread owns 16 d's)
    float o[16];
#pragma unroll
    for (int i = 0; i < 16; i++) o[i] = 0.f;
    const int dBase = half << 4;
    for (int m = 0; m < 64; m++) {
        float p = sp[n][m];
#pragma unroll
        for (int d4 = 0; d4 < 4; d4++) {
            float4 v4 = *(const float4*)&sv[m][dBase + (d4 << 2)];
            o[d4 * 4 + 0] += p * v4.x; o[d4 * 4 + 1] += p * v4.y;
            o[d4 * 4 + 2] += p * v4.z; o[d4 * 4 + 3] += p * v4.w;
        }
    }
    float* op = aout + ((size_t)b * 64 + n) * 256 + h * 32 + dBase;
#pragma unroll
    for (int d4 = 0; d4 < 4; d4++)
        *(float4*)(op + (d4 << 2)) =
            make_float4(o[d4 * 4 + 0], o[d4 * 4 + 1], o[d4 * 4 + 2], o[d4 * 4 + 3]);
}

// ---------------------------------------------------------------------------
// Launch: qkv GEMM -> attention -> proj GEMM. All on default stream,
// graph-capturable (kernel launches only, no sync, no alloc).
// ---------------------------------------------------------------------------
extern "C" void kernel_launch(void* const* d_in, const int* in_sizes, int n_in,
                              void* d_out, int out_size)
{
    const float* x   = (const float*)d_in[0];  // [8192,64,256]
    const float* qw  = (const float*)d_in[1];  // [768,256]
    const float* qb  = (const float*)d_in[2];  // [768]
    const float* pw  = (const float*)d_in[3];  // [256,256]
    const float* pb  = (const float*)d_in[4];  // [256]
    const float* tab = (const float*)d_in[5];  // [225,8]
    const int*   rpi = (const int*)d_in[6];    // [64,64]
    float* out = (float*)d_out;                // [8192,64,256]

    float* qkv  = nullptr;
    float* aout = nullptr;
    cudaGetSymbolAddress((void**)&qkv,  g_qkv);
    cudaGetSymbolAddress((void**)&aout, g_aout);

    // QKV projection: [524288,256] @ [768,256]^T + b
    dim3 g1(768 / BN, (8192 * 64) / BM);   // (12, 8192)
    gemm_bias_kernel<<<g1, 256>>>(x, qw, qb, qkv, 768);

    // Windowed attention per (head, window)
    dim3 g2(8, 8192);
    attn_kernel<<<g2, 128>>>(qkv, tab, rpi, aout);

    // Output projection: [524288,256] @ [256,256]^T + b
    dim3 g3(256 / BN, (8192 * 64) / BM);   // (4, 8192)
    gemm_bias_kernel<<<g3, 256>>>(aout, pw, pb, out, 256);
}

// round 2
// speedup vs baseline: 2.0894x; 2.0894x over previous
#include <cuda_runtime.h>
#include <cstdint>

// ---------------------------------------------------------------------------
// LeWinAttention round 2: GEMMs on tensor pipe via mma.sync tf32 (m16n8k8).
// qkv GEMM [524288,256]@[768,256]^T -> attention (fp32, unchanged) -> proj.
// ---------------------------------------------------------------------------

#define BM 128
#define BN 64
#define BK 32

// Scratch (allocation-free rule: __device__ globals)
__device__ float g_qkv[402653184];   // 8192*64*768  (1.5 GB)
__device__ float g_aout[134217728];  // 8192*64*256  (512 MB)

__device__ __forceinline__ unsigned f2tf32(float f) {
    unsigned u;
    asm("cvt.rna.tf32.f32 %0, %1;" : "=r"(u) : "f"(f));
    return u;
}

__device__ __forceinline__ void mma_tf32(float* d, const unsigned* a, const unsigned* b) {
    asm volatile(
        "mma.sync.aligned.m16n8k8.row.col.f32.tf32.tf32.f32 "
        "{%0,%1,%2,%3}, {%4,%5,%6,%7}, {%8,%9}, {%0,%1,%2,%3};"
        : "+f"(d[0]), "+f"(d[1]), "+f"(d[2]), "+f"(d[3])
        : "r"(a[0]), "r"(a[1]), "r"(a[2]), "r"(a[3]), "r"(b[0]), "r"(b[1]));
}

// ---------------------------------------------------------------------------
// C[M,Nc] = A[M,256] @ W[Nc,256]^T + bias[Nc]   (tf32 tensor cores)
// 256 threads; warp grid 4(m) x 2(n); warp tile 32x32 = 2 x 4 mma tiles.
// ---------------------------------------------------------------------------
__global__ void __launch_bounds__(256)
gemm_tc_kernel(const float* __restrict__ A, const float* __restrict__ W,
               const float* __restrict__ bias, float* __restrict__ C, int Nc)
{
    __shared__ unsigned As[BM][BK + 4];  // tf32 bits, stride 36 -> conflict-free frags
    __shared__ unsigned Ws[BN][BK + 4];

    const int t    = threadIdx.x;
    const int lane = t & 31;
    const int gid  = lane >> 2;   // group id 0..7
    const int tig  = lane & 3;    // thread-in-group 0..3
    const int w    = t >> 5;
    const int wm   = w & 3;       // warp m index (4)
    const int wn   = w >> 2;      // warp n index (2)

    const size_t mBase = (size_t)blockIdx.y * BM;
    const int    nBase = blockIdx.x * BN;

    const float* Ap = A + mBase * 256;
    const float* Wp = W + (size_t)nBase * 256;

    float acc[2][4][4];
#pragma unroll
    for (int mt = 0; mt < 2; mt++)
#pragma unroll
        for (int nt = 0; nt < 4; nt++)
#pragma unroll
            for (int i = 0; i < 4; i++) acc[mt][nt][i] = 0.f;

    // per-thread global load mapping (row-major, 8 float4 per 32-col row)
    // A: 1024 float4 -> 4 per thread; W: 512 float4 -> 2 per thread
    int ar[4], ac[4], wr[2], wc[2];
#pragma unroll
    for (int i = 0; i < 4; i++) { int f = t + (i << 8); ar[i] = f >> 3; ac[i] = (f & 7) << 2; }
#pragma unroll
    for (int i = 0; i < 2; i++) { int f = t + (i << 8); wr[i] = f >> 3; wc[i] = (f & 7) << 2; }

    for (int k0 = 0; k0 < 256; k0 += BK) {
        float4 av[4], wv[2];
#pragma unroll
        for (int i = 0; i < 4; i++)
            av[i] = *(const float4*)(Ap + (size_t)ar[i] * 256 + k0 + ac[i]);
#pragma unroll
        for (int i = 0; i < 2; i++)
            wv[i] = *(const float4*)(Wp + (size_t)wr[i] * 256 + k0 + wc[i]);

        __syncthreads();  // WAR: previous iteration's frag reads done
#pragma unroll
        for (int i = 0; i < 4; i++) {
            uint4 u = make_uint4(f2tf32(av[i].x), f2tf32(av[i].y),
                                 f2tf32(av[i].z), f2tf32(av[i].w));
            *(uint4*)&As[ar[i]][ac[i]] = u;
        }
#pragma unroll
        for (int i = 0; i < 2; i++) {
            uint4 u = make_uint4(f2tf32(wv[i].x), f2tf32(wv[i].y),
                                 f2tf32(wv[i].z), f2tf32(wv[i].w));
            *(uint4*)&Ws[wr[i]][wc[i]] = u;
        }
        __syncthreads();

#pragma unroll
        for (int kk = 0; kk < 4; kk++) {
            const int k8 = kk << 3;
            unsigned af[2][4], bf[4][2];
#pragma unroll
            for (int mt = 0; mt < 2; mt++) {
                int r0 = wm * 32 + mt * 16 + gid;
                af[mt][0] = As[r0][k8 + tig];
                af[mt][1] = As[r0 + 8][k8 + tig];
                af[mt][2] = As[r0][k8 + tig + 4];
                af[mt][3] = As[r0 + 8][k8 + tig + 4];
            }
#pragma unroll
            for (int nt = 0; nt < 4; nt++) {
                int n0 = wn * 32 + nt * 8 + gid;
                bf[nt][0] = Ws[n0][k8 + tig];
                bf[nt][1] = Ws[n0][k8 + tig + 4];
            }
#pragma unroll
            for (int mt = 0; mt < 2; mt++)
#pragma unroll
                for (int nt = 0; nt < 4; nt++)
                    mma_tf32(acc[mt][nt], af[mt], bf[nt]);
        }
    }

    // epilogue: + bias, float2 stores
#pragma unroll
    for (int mt = 0; mt < 2; mt++) {
#pragma unroll
        for (int nt = 0; nt < 4; nt++) {
            int col = nBase + wn * 32 + nt * 8 + (tig << 1);
            float b0 = bias[col], b1 = bias[col + 1];
            size_t r0 = mBase + wm * 32 + mt * 16 + gid;
            *(float2*)(C + r0 * Nc + col) =
                make_float2(acc[mt][nt][0] + b0, acc[mt][nt][1] + b1);
            *(float2*)(C + (r0 + 8) * Nc + col) =
                make_float2(acc[mt][nt][2] + b0, acc[mt][nt][3] + b1);
        }
    }
}

// ---------------------------------------------------------------------------
// Attention: one CTA per (head, window). Unchanged from round 1 (fp32).
// ---------------------------------------------------------------------------
__global__ void __launch_bounds__(128)
attn_kernel(const float* __restrict__ qkv, const float* __restrict__ table,
            const int* __restrict__ rpi, float* __restrict__ aout)
{
    __shared__ float sq[64][36];
    __shared__ float sk[64][36];
    __shared__ float sv[64][36];
    __shared__ float sp[64][65];

    const int h = blockIdx.x;
    const int b = blockIdx.y;
    const int t = threadIdx.x;

    const float* base = qkv + (size_t)b * 64 * 768 + h * 32;
    for (int idx = t; idx < 64 * 8; idx += 128) {
        int n  = idx >> 3;
        int c4 = (idx & 7) << 2;
        const float* rp = base + n * 768 + c4;
        float4 q4 = *(const float4*)(rp);
        float4 k4 = *(const float4*)(rp + 256);
        float4 v4 = *(const float4*)(rp + 512);
        *(float4*)&sq[n][c4] = q4;
        *(float4*)&sk[n][c4] = k4;
        *(float4*)&sv[n][c4] = v4;
    }
    __syncthreads();

    const int n    = t & 63;
    const int half = t >> 6;

    float qreg[32];
#pragma unroll
    for (int d4 = 0; d4 < 8; d4++) {
        float4 q4 = *(const float4*)&sq[n][d4 << 2];
        qreg[d4 * 4 + 0] = q4.x; qreg[d4 * 4 + 1] = q4.y;
        qreg[d4 * 4 + 2] = q4.z; qreg[d4 * 4 + 3] = q4.w;
    }

    const float scale = 0.17677669529663687f;  // 32^-0.5
#pragma unroll 4
    for (int mm = 0; mm < 32; mm++) {
        int m = (half << 5) + mm;
        float s = 0.f;
#pragma unroll
        for (int d4 = 0; d4 < 8; d4++) {
            float4 k4 = *(const float4*)&sk[m][d4 << 2];
            s += qreg[d4 * 4 + 0] * k4.x + qreg[d4 * 4 + 1] * k4.y
               + qreg[d4 * 4 + 2] * k4.z + qreg[d4 * 4 + 3] * k4.w;
        }
        int idx = rpi[n * 64 + m];
        sp[n][m] = s * scale + table[idx * 8 + h];
    }
    __syncthreads();

    if (t < 64) {
        float mx = -1e30f;
#pragma unroll
        for (int m = 0; m < 64; m++) mx = fmaxf(mx, sp[t][m]);
        float sum = 0.f;
#pragma unroll
        for (int m = 0; m < 64; m++) {
            float e = __expf(sp[t][m] - mx);
            sp[t][m] = e;
            sum += e;
        }
        float inv = 1.f / sum;
#pragma unroll
        for (int m = 0; m < 64; m++) sp[t][m] *= inv;
    }
    __syncthreads();

    float o[16];
#pragma unroll
    for (int i = 0; i < 16; i++) o[i] = 0.f;
    const int dBase = half << 4;
    for (int m = 0; m < 64; m++) {
        float p = sp[n][m];
#pragma unroll
        for (int d4 = 0; d4 < 4; d4++) {
            float4 v4 = *(const float4*)&sv[m][dBase + (d4 << 2)];
            o[d4 * 4 + 0] += p * v4.x; o[d4 * 4 + 1] += p * v4.y;
            o[d4 * 4 + 2] += p * v4.z; o[d4 * 4 + 3] += p * v4.w;
        }
    }
    float* op = aout + ((size_t)b * 64 + n) * 256 + h * 32 + dBase;
#pragma unroll
    for (int d4 = 0; d4 < 4; d4++)
        *(float4*)(op + (d4 << 2)) =
            make_float4(o[d4 * 4 + 0], o[d4 * 4 + 1], o[d4 * 4 + 2], o[d4 * 4 + 3]);
}

// ---------------------------------------------------------------------------
extern "C" void kernel_launch(void* const* d_in, const int* in_sizes, int n_in,
                              void* d_out, int out_size)
{
    const float* x   = (const float*)d_in[0];  // [8192,64,256]
    const float* qw  = (const float*)d_in[1];  // [768,256]
    const float* qb  = (const float*)d_in[2];  // [768]
    const float* pw  = (const float*)d_in[3];  // [256,256]
    const float* pb  = (const float*)d_in[4];  // [256]
    const float* tab = (const float*)d_in[5];  // [225,8]
    const int*   rpi = (const int*)d_in[6];    // [64,64]
    float* out = (float*)d_out;                // [8192,64,256]

    float* qkv  = nullptr;
    float* aout = nullptr;
    cudaGetSymbolAddress((void**)&qkv,  g_qkv);
    cudaGetSymbolAddress((void**)&aout, g_aout);

    // QKV projection: [524288,256] @ [768,256]^T + b
    dim3 g1(768 / BN, (8192 * 64) / BM);   // (12, 4096)
    gemm_tc_kernel<<<g1, 256>>>(x, qw, qb, qkv, 768);

    // Windowed attention per (head, window)
    dim3 g2(8, 8192);
    attn_kernel<<<g2, 128>>>(qkv, tab, rpi, aout);

    // Output projection: [524288,256] @ [256,256]^T + b
    dim3 g3(256 / BN, (8192 * 64) / BM);   // (4, 4096)
    gemm_tc_kernel<<<g3, 256>>>(aout, pw, pb, out, 256);
}